// round 2
// baseline (speedup 1.0000x reference)
#include <cuda_runtime.h>

#define HID   256
#define BATCH 16
#define TLEN  1024
#define SEQ   256
#define NPMAX 5184
#define RELAY_TPB 256
#define NCHUNK 21           // ceil(5151/256)
#define WPB 8               // warps per relay block

// ---------------- scratch (static device globals; no allocation) ------------
__device__ float g_density[NPMAX];
__device__ float g_cb[BATCH * HID];
__device__ float g_dsum;
__device__ float g_part[BATCH * NCHUNK * WPB * TLEN];   // ~11 MB

// ---------------- fast-math helpers ----------------------------------------
__device__ __forceinline__ float ex2f(float x) {
    float y; asm("ex2.approx.ftz.f32 %0, %1;" : "=f"(y) : "f"(x)); return y;
}
__device__ __forceinline__ float rcpf(float x) {
    float y; asm("rcp.approx.ftz.f32 %0, %1;" : "=f"(y) : "f"(x)); return y;
}

// ============================================================================
// K1: density MLP (batch-invariant).  One block = 32 mesh points.
//   x = relu(mesh@Win + bin); 3x residual (h += relu(h@W+b)); sigmoid head.
//   Also replicates density + mesh into the output tensor (16x broadcast).
// ============================================================================
__global__ __launch_bounds__(256, 1)
void density_kernel(const float* __restrict__ mesh,
                    const float* __restrict__ Win,
                    const float* __restrict__ bin,
                    const float* __restrict__ Wr,
                    const float* __restrict__ br,
                    const float* __restrict__ Wout,
                    const float* __restrict__ bout,
                    float* __restrict__ out_density,
                    float* __restrict__ out_mesh,
                    int NP)
{
    __shared__ __align__(16) float hbuf[32 * HID];   // 32 KB
    __shared__ float smesh[64];

    const int tid = threadIdx.x;
    const int j   = tid;                 // output feature column owned by thread
    const int p0  = blockIdx.x * 32;

    if (tid < 64) {
        int idx = p0 * 2 + tid;
        smesh[tid] = (idx < NP * 2) ? mesh[idx] : 0.f;
    }
    __syncthreads();

    // ---- stage 0: input projection ----
    {
        float w0 = Win[j], w1 = Win[HID + j], bj = bin[j];
        #pragma unroll
        for (int p = 0; p < 32; p++) {
            float v = fmaf(smesh[2*p], w0, fmaf(smesh[2*p+1], w1, bj));
            hbuf[p * HID + j] = fmaxf(v, 0.f);
        }
    }
    __syncthreads();

    // ---- 3 residual layers ----
    for (int l = 0; l < 3; l++) {
        const float* __restrict__ W = Wr + l * HID * HID;
        float acc[32];
        #pragma unroll
        for (int p = 0; p < 32; p++) acc[p] = 0.f;

        for (int k = 0; k < HID; k += 4) {
            float wa = W[(k+0) * HID + j];
            float wb = W[(k+1) * HID + j];
            float wc = W[(k+2) * HID + j];
            float wd = W[(k+3) * HID + j];
            #pragma unroll
            for (int p = 0; p < 32; p++) {
                float4 h4 = *reinterpret_cast<const float4*>(&hbuf[p * HID + k]);
                float a = acc[p];
                a = fmaf(h4.x, wa, a);
                a = fmaf(h4.y, wb, a);
                a = fmaf(h4.z, wc, a);
                a = fmaf(h4.w, wd, a);
                acc[p] = a;
            }
        }
        float bb = br[l * HID + j];
        __syncthreads();
        #pragma unroll
        for (int p = 0; p < 32; p++)
            hbuf[p * HID + j] += fmaxf(acc[p] + bb, 0.f);
        __syncthreads();
    }

    // ---- output head: warp w reduces points 4w..4w+3 ----
    const int warp = tid >> 5, lane = tid & 31;
    float wv[8];
    #pragma unroll
    for (int i = 0; i < 8; i++) wv[i] = Wout[lane + i * 32];
    float b0 = bout[0];

    #pragma unroll
    for (int q = 0; q < 4; q++) {
        int p = warp * 4 + q;
        float d = 0.f;
        #pragma unroll
        for (int i = 0; i < 8; i++)
            d = fmaf(hbuf[p * HID + lane + i * 32], wv[i], d);
        #pragma unroll
        for (int o = 16; o > 0; o >>= 1)
            d += __shfl_xor_sync(0xffffffffu, d, o);
        if (lane == 0 && p0 + p < NP) {
            float dens = 1.f / (1.f + expf(-(d + b0)));
            g_density[p0 + p] = dens;
            #pragma unroll
            for (int b = 0; b < BATCH; b++)
                out_density[b * NP + p0 + p] = dens;
        }
    }

    // ---- mesh broadcast output ----
    if (tid < 64) {
        int idx = p0 * 2 + tid;
        if (idx < NP * 2) {
            float v = smesh[tid];
            #pragma unroll
            for (int b = 0; b < BATCH; b++)
                out_mesh[b * NP * 2 + idx] = v;
        }
    }
}

// ============================================================================
// K2: encoder context -> cb[b] = ctx@Wc + bm  (one block per batch).
//     Extra block (b == BATCH) computes dsum = sum(density).
// ============================================================================
__global__ void encoder_kernel(const float* __restrict__ enc_in,
                               const float* __restrict__ mask,
                               const float* __restrict__ Ws,
                               const float* __restrict__ bs,
                               const float* __restrict__ Wc,
                               const float* __restrict__ bm,
                               int NP)
{
    const int b = blockIdx.x;
    const int j = threadIdx.x;

    if (b == BATCH) {   // dsum reduction
        __shared__ float red[256];
        float s = 0.f;
        for (int i = j; i < NP; i += 256) s += g_density[i];
        red[j] = s;
        __syncthreads();
        for (int o = 128; o > 0; o >>= 1) {
            if (j < o) red[j] += red[j + o];
            __syncthreads();
        }
        if (j == 0) g_dsum = red[0];
        return;
    }

    __shared__ float se[SEQ * 2];
    __shared__ float sm[SEQ];
    __shared__ float sctx[HID];

    for (int i = j; i < SEQ * 2; i += 256) se[i] = enc_in[b * SEQ * 2 + i];
    sm[j] = mask[b * SEQ + j];
    __syncthreads();

    float w0 = Ws[j], w1 = Ws[HID + j], bj = bs[j];
    float acc = 0.f, msum = 0.f;
    for (int s = 0; s < SEQ; s++) {
        float mk = sm[s];
        float v  = fmaf(se[2*s], w0, fmaf(se[2*s+1], w1, bj));
        acc  = fmaf(mk, fmaxf(v, 0.f), acc);
        msum += mk;
    }
    sctx[j] = acc / fmaxf(msum, 1.f);
    __syncthreads();

    float cb = bm[j];
    for (int k = 0; k < HID; k++)
        cb = fmaf(sctx[k], Wc[k * HID + j], cb);
    g_cb[b * HID + j] = cb;
}

// ============================================================================
// K3: relay scan. grid = (NCHUNK, BATCH), 256 threads, 1 mesh point / lane.
//     Prologue fuses the initial_states computation (z@Wo -> tanh).
//     Main loop: per-step smooth relay update + warp reduction of dens*s into
//     per-(warp,t) partials in g_part (no atomics, no block barriers).
// ============================================================================
__global__ __launch_bounds__(RELAY_TPB)
void relay_kernel(const float* __restrict__ mesh,
                  const float* __restrict__ dec,
                  const float* __restrict__ Wm,
                  const float* __restrict__ Wo,
                  const float* __restrict__ bo,
                  float* __restrict__ out_init,
                  int NP)
{
    __shared__ float sh_h[TLEN];
    __shared__ float s_cb[HID], s_wm0[HID], s_wm1[HID], s_wm2[HID], s_wo[HID];

    const int tid   = threadIdx.x;
    const int chunk = blockIdx.x;
    const int b     = blockIdx.y;
    const int p     = chunk * RELAY_TPB + tid;
    const bool valid = (p < NP);

    for (int i = tid; i < TLEN; i += RELAY_TPB) sh_h[i] = dec[b * TLEN + i];
    s_cb[tid]  = g_cb[b * HID + tid];
    s_wm0[tid] = Wm[tid];
    s_wm1[tid] = Wm[HID + tid];
    s_wm2[tid] = Wm[2 * HID + tid];
    s_wo[tid]  = Wo[tid];
    __syncthreads();

    float beta  = valid ? mesh[2*p]     : 0.f;
    float alpha = valid ? mesh[2*p + 1] : 0.f;
    float dens  = valid ? g_density[p]  : 0.f;

    // ---- fused initial_states ----
    float acc = 0.f;
    #pragma unroll 8
    for (int jj = 0; jj < HID; jj++) {
        float pre = fmaf(beta, s_wm0[jj],
                    fmaf(alpha, s_wm1[jj],
                    fmaf(dens,  s_wm2[jj], s_cb[jj])));
        acc = fmaf(fmaxf(pre, 0.f), s_wo[jj], acc);
    }
    float s = tanhf(acc + bo[0]);
    if (valid) out_init[b * NP + p] = s;
    if (!valid) s = 0.f;

    // sigmoid(x/0.001) = 1/(1 + 2^(-x*1000*log2(e)))
    const float SLG = 1442.69504f;      // 1000 * log2(e)
    const int warp = tid >> 5, lane = tid & 31;
    float* __restrict__ prow =
        g_part + (((b * NCHUNK + chunk) * WPB) + warp) * TLEN;

    #pragma unroll 2
    for (int t = 0; t < TLEN; t++) {
        float ht = sh_h[t];
        // exact small-difference first, then scale (avoids cancellation drift)
        float eu = ex2f((alpha - ht) * SLG);
        float ed = ex2f((ht - beta)  * SLG);
        float wu = rcpf(1.f + eu);
        float wd = rcpf(1.f + ed);
        s = fmaf(wu,  1.f - s, s);
        s = fmaf(wd, -1.f - s, s);
        float c = dens * s;
        c += __shfl_xor_sync(0xffffffffu, c, 16);
        c += __shfl_xor_sync(0xffffffffu, c, 8);
        c += __shfl_xor_sync(0xffffffffu, c, 4);
        c += __shfl_xor_sync(0xffffffffu, c, 2);
        c += __shfl_xor_sync(0xffffffffu, c, 1);
        if (lane == 0) prow[t] = c;
    }
}

// ============================================================================
// K4: reduce partials -> m, then b_out = h_scale*h + m_scale*m + m_offset.
// ============================================================================
__global__ void finalize_kernel(const float* __restrict__ dec,
                                const float* __restrict__ hsr,
                                const float* __restrict__ msr,
                                const float* __restrict__ mor,
                                float* __restrict__ out_b,
                                float* __restrict__ out_m)
{
    const int idx = blockIdx.x * 256 + threadIdx.x;
    const int b = idx >> 10;
    const int t = idx & (TLEN - 1);

    float msum = 0.f;
    const float* __restrict__ base = g_part + b * NCHUNK * WPB * TLEN + t;
    #pragma unroll 8
    for (int w = 0; w < NCHUNK * WPB; w++)
        msum += base[w * TLEN];

    float inv_d = 1.f / g_dsum;
    float m  = msum * inv_d;
    float h  = dec[idx];
    float hs = 10.f / (1.f + expf(-hsr[0]));
    float ms = 10.f / (1.f + expf(-msr[0]));
    float mo = -10.f + 20.f / (1.f + expf(-mor[0]));

    out_m[idx] = m;
    out_b[idx] = fmaf(hs, h, fmaf(ms, m, mo));
}

// ============================================================================
// launch
// ============================================================================
extern "C" void kernel_launch(void* const* d_in, const int* in_sizes, int n_in,
                              void* d_out, int out_size)
{
    const float* enc_in = (const float*)d_in[0];    // (16,256,2)
    const float* dec    = (const float*)d_in[1];    // (16,1024,1)
    const float* mask   = (const float*)d_in[2];    // (16,256)
    const float* mesh   = (const float*)d_in[3];    // (NP,2)
    const float* Win    = (const float*)d_in[4];
    const float* bin    = (const float*)d_in[5];
    const float* Wr     = (const float*)d_in[6];
    const float* br     = (const float*)d_in[7];
    const float* Wout   = (const float*)d_in[8];
    const float* bout   = (const float*)d_in[9];
    const float* Ws     = (const float*)d_in[10];
    const float* bs     = (const float*)d_in[11];
    const float* Wm     = (const float*)d_in[12];
    const float* Wc     = (const float*)d_in[13];
    const float* bm     = (const float*)d_in[14];
    const float* Wo     = (const float*)d_in[15];
    const float* bo     = (const float*)d_in[16];
    const float* hsr    = (const float*)d_in[17];
    const float* msr    = (const float*)d_in[18];
    const float* mor    = (const float*)d_in[19];

    const int NP = in_sizes[3] / 2;                 // 5151

    float* O        = (float*)d_out;
    float* out_b    = O;                            // (16,1024)
    float* out_dens = O + BATCH * TLEN;             // (16,NP)
    float* out_m    = out_dens + BATCH * NP;        // (16,1024)
    float* out_init = out_m + BATCH * TLEN;         // (16,NP)
    float* out_mesh = out_init + BATCH * NP;        // (16,NP,2)

    density_kernel<<<(NP + 31) / 32, 256>>>(mesh, Win, bin, Wr, br, Wout, bout,
                                            out_dens, out_mesh, NP);
    encoder_kernel<<<BATCH + 1, 256>>>(enc_in, mask, Ws, bs, Wc, bm, NP);
    relay_kernel<<<dim3(NCHUNK, BATCH), RELAY_TPB>>>(mesh, dec, Wm, Wo, bo,
                                                     out_init, NP);
    finalize_kernel<<<(BATCH * TLEN) / 256, 256>>>(dec, hsr, msr, mor,
                                                   out_b, out_m);
}